// round 9
// baseline (speedup 1.0000x reference)
#include <cuda_runtime.h>
#include <cuda_bf16.h>

#define NX 2048
#define NY 4096
#define ROWS 8
#define FULLMASK 0xffffffffu

// Build c1/c2 from ha, hb, inv = 1/(ha*hb*(ha+hb)).
// kind: 0 = left one-sided, 1 = centered, 2 = right one-sided
__device__ __forceinline__ void coeffs_from_inv(float ha, float hb, float inv, int kind,
                                                float c1[3], float c2[3]) {
    float sab = ha + hb;
    float i_a  = hb  * inv;
    float i_ab = sab * inv;
    float i_b  = ha  * inv;
    c2[0] = 2.0f * i_a;
    c2[1] = -2.0f * i_ab;
    c2[2] = 2.0f * i_b;
    if (kind == 0) {
        c1[0] = -(2.0f * ha + hb) * i_a;
        c1[1] = sab * i_ab;
        c1[2] = -ha * i_b;
    } else if (kind == 2) {
        c1[0] = hb * i_a;
        c1[1] = -sab * i_ab;
        c1[2] = (ha + 2.0f * hb) * i_b;
    } else {
        c1[0] = -hb * i_a;
        c1[1] = (hb - ha) * i_ab;
        c1[2] = ha * i_b;
    }
}

// Each thread: 4 consecutive j (float4) x 8 i rows, rolling 4-row window.
// mu is pre-folded into all second-derivative coefficients.
__global__ __launch_bounds__(128, 6) void rhs_kernel(const float* __restrict__ state,
                                                     const float* __restrict__ xg,
                                                     const float* __restrict__ yg,
                                                     const float* __restrict__ mu_p,
                                                     float* __restrict__ out) {
    const int lane = threadIdx.x;                       // 0..31
    const int jg = blockIdx.x * 32 + lane;
    const int j0 = jg * 4;
    const int it = blockIdx.y * blockDim.y + threadIdx.y;
    const int i0 = it * ROWS;

    const float* __restrict__ u = state;
    const float* __restrict__ v = state + NX * NY;

    const bool eL = (j0 == 0);
    const bool eR = (j0 == NY - 4);
    const bool firstB = (i0 == 0);
    const bool lastB  = (i0 == NX - ROWS);
    const float mu = mu_p[0];

    // ---- rolling window prologue: rows clamp(i0-1), i0, i0+1, i0+2 ----
    int rA = max(i0 - 1, 0);
    float4 Au = *(const float4*)(u + rA * NY + j0);
    float4 Av = *(const float4*)(v + rA * NY + j0);
    float4 Bu = *(const float4*)(u + i0 * NY + j0);
    float4 Bv = *(const float4*)(v + i0 * NY + j0);
    float4 Cu = *(const float4*)(u + (i0 + 1) * NY + j0);
    float4 Cv = *(const float4*)(v + (i0 + 1) * NY + j0);
    float4 Du = *(const float4*)(u + (i0 + 2) * NY + j0);
    float4 Dv = *(const float4*)(v + (i0 + 2) * NY + j0);

    // ---- y coefficients (pair-batched: 2 RCPs); mu folded into C2Y ----
    float C1Y0[4], C1Y1[4], C1Y2[4], C2Y0[4], C2Y1[4], C2Y2[4];
    {
        float ys[6];
#pragma unroll
        for (int t = 0; t < 6; t++)
            ys[t] = yg[min(max(j0 - 1 + t, 0), NY - 1)];
        float HA[4], HB[4], T[4];
        int KND[4];
#pragma unroll
        for (int l = 0; l < 4; l++) {
            float g0 = ys[l], g1 = ys[l + 1], g2 = ys[l + 2];
            int kind = 1;
            if (l == 0 && eL) { g0 = ys[1]; g1 = ys[2]; g2 = ys[3]; kind = 0; }
            if (l == 3 && eR) { g0 = ys[2]; g1 = ys[3]; g2 = ys[4]; kind = 2; }
            HA[l] = g1 - g0;
            HB[l] = g2 - g1;
            T[l] = HA[l] * HB[l] * (HA[l] + HB[l]);
            KND[l] = kind;
        }
        float ip01 = 1.0f / (T[0] * T[1]);
        float ip23 = 1.0f / (T[2] * T[3]);
        float INV[4] = {ip01 * T[1], ip01 * T[0], ip23 * T[3], ip23 * T[2]};
#pragma unroll
        for (int l = 0; l < 4; l++) {
            float c1[3], c2[3];
            coeffs_from_inv(HA[l], HB[l], INV[l], KND[l], c1, c2);
            C1Y0[l] = c1[0]; C1Y1[l] = c1[1]; C1Y2[l] = c1[2];
            C2Y0[l] = mu * c2[0]; C2Y1[l] = mu * c2[1]; C2Y2[l] = mu * c2[2];
        }
    }

    // ---- x coefficients: each lane computes ONE row's set (row = lane&7), 1 RCP ----
    float cx1p[3], cx2p[3];
    {
        int ii = i0 + (lane & 7);
        int s = min(max(ii - 1, 0), NX - 3);
        int kind = (ii == 0) ? 0 : ((ii == NX - 1) ? 2 : 1);
        float g0 = xg[s], g1 = xg[s + 1], g2 = xg[s + 2];
        float ha = g1 - g0, hb = g2 - g1;
        float inv = 1.0f / (ha * hb * (ha + hb));
        coeffs_from_inv(ha, hb, inv, kind, cx1p, cx2p);
        cx2p[0] *= mu; cx2p[1] *= mu; cx2p[2] *= mu;
    }

    // j-dependent boundary predicates (loop-invariant over rows)
    bool zj[4], zlast[4];
#pragma unroll
    for (int l = 0; l < 4; l++) {
        zj[l]    = (j0 + l == 0);
        zlast[l] = (j0 + l == NY - 1);
    }

    int off = i0 * NY + j0;

#pragma unroll
    for (int m = 0; m < ROWS; m++) {
        const int i = i0 + m;

        // x coefficients for this row: broadcast within 8-lane groups
        const float cx10 = __shfl_sync(FULLMASK, cx1p[0], m, 8);
        const float cx11 = __shfl_sync(FULLMASK, cx1p[1], m, 8);
        const float cx12 = __shfl_sync(FULLMASK, cx1p[2], m, 8);
        const float cx20 = __shfl_sync(FULLMASK, cx2p[0], m, 8);
        const float cx21 = __shfl_sync(FULLMASK, cx2p[1], m, 8);
        const float cx22 = __shfl_sync(FULLMASK, cx2p[2], m, 8);

        // select x-stencil data rows (window: A=i-1, B=i, C=i+1, D=i+2)
        float4 u0 = Au, u1 = Bu, u2 = Cu;
        float4 v0 = Av, v1 = Bv, v2 = Cv;
        if (m == 0 && firstB) {            // i==0: data rows 0,1,2
            u0 = Bu; u1 = Cu; u2 = Du;
            v0 = Bv; v1 = Cv; v2 = Dv;
        }
        if (m == ROWS - 1 && lastB) {      // i==NX-1: data rows NX-3,NX-2,NX-1
            float4 zu = *(const float4*)(u + (NX - 3) * NY + j0);
            float4 zv = *(const float4*)(v + (NX - 3) * NY + j0);
            u0 = zu; u1 = Au; u2 = Bu;
            v0 = zv; v1 = Av; v2 = Bv;
        }

        // center row (global i) is always B
        const float4 uc = Bu;
        const float4 vc = Bv;

        // y-neighbors via warp shuffle, patched at warp edges
        float uLm = __shfl_up_sync(FULLMASK, uc.w, 1);
        float vLm = __shfl_up_sync(FULLMASK, vc.w, 1);
        float uRm = __shfl_down_sync(FULLMASK, uc.x, 1);
        float vRm = __shfl_down_sync(FULLMASK, vc.x, 1);
        if (lane == 0 && j0 > 0) {
            uLm = u[off - 1];
            vLm = v[off - 1];
        }
        if (lane == 31 && j0 + 4 < NY) {
            uRm = u[off + 4];
            vRm = v[off + 4];
        }

        const float u_vals[6] = {uLm, uc.x, uc.y, uc.z, uc.w, uRm};
        const float v_vals[6] = {vLm, vc.x, vc.y, vc.z, vc.w, vRm};
        const float AX0[4] = {u0.x, u0.y, u0.z, u0.w};
        const float AX1[4] = {u1.x, u1.y, u1.z, u1.w};
        const float AX2[4] = {u2.x, u2.y, u2.z, u2.w};
        const float BX0[4] = {v0.x, v0.y, v0.z, v0.w};
        const float BX1[4] = {v1.x, v1.y, v1.z, v1.w};
        const float BX2[4] = {v2.x, v2.y, v2.z, v2.w};

        float du[4], dv[4];
#pragma unroll
        for (int l = 0; l < 4; l++) {
            float f0 = u_vals[l], f1 = u_vals[l + 1], f2 = u_vals[l + 2];
            float g0 = v_vals[l], g1 = v_vals[l + 1], g2 = v_vals[l + 2];
            if (eL && l == 0) {         // one-sided at j=0: data points 0,1,2
                f0 = u_vals[1]; f1 = u_vals[2]; f2 = u_vals[3];
                g0 = v_vals[1]; g1 = v_vals[2]; g2 = v_vals[3];
            }
            if (eR && l == 3) {         // one-sided at j=NY-1: data NY-3..NY-1
                f0 = u_vals[2]; f1 = u_vals[3]; f2 = u_vals[4];
                g0 = v_vals[2]; g1 = v_vals[3]; g2 = v_vals[4];
            }

            float d1yu = C1Y0[l] * f0 + C1Y1[l] * f1 + C1Y2[l] * f2;
            float d2yu = C2Y0[l] * f0 + C2Y1[l] * f1 + C2Y2[l] * f2;   // mu-scaled
            float d1yv = C1Y0[l] * g0 + C1Y1[l] * g1 + C1Y2[l] * g2;
            float d2yv = C2Y0[l] * g0 + C2Y1[l] * g1 + C2Y2[l] * g2;   // mu-scaled

            float d1xu = cx10 * AX0[l] + cx11 * AX1[l] + cx12 * AX2[l];
            float d2xu = cx20 * AX0[l] + cx21 * AX1[l] + cx22 * AX2[l]; // mu-scaled
            float d1xv = cx10 * BX0[l] + cx11 * BX1[l] + cx12 * BX2[l];
            float d2xv = cx20 * BX0[l] + cx21 * BX1[l] + cx22 * BX2[l]; // mu-scaled

            float ucen = u_vals[l + 1];
            float vcen = v_vals[l + 1];

            du[l] = (d2yu + d2xu) - ucen * d1xu - vcen * d1yu + 0.01f;
            dv[l] = (d2yv + d2xv) - ucen * d1xv - vcen * d1yv;

            bool zi = (m == 0) && firstB;            // i == 0
            if (zj[l] || zi) { du[l] = 0.0f; dv[l] = 0.0f; }
            if (zlast[l]) du[l] = 0.0f;
        }

        *(float4*)(out + off) = make_float4(du[0], du[1], du[2], du[3]);
        *(float4*)(out + NX * NY + off) = make_float4(dv[0], dv[1], dv[2], dv[3]);

        // shift window and prefetch next row (D becomes row i+3 of new window)
        if (m < ROWS - 1) {
            Au = Bu; Bu = Cu; Cu = Du;
            Av = Bv; Bv = Cv; Cv = Dv;
            int r = min(i + 3, NX - 1);
            Du = *(const float4*)(u + r * NY + j0);
            Dv = *(const float4*)(v + r * NY + j0);
            off += NY;
        }
    }
}

extern "C" void kernel_launch(void* const* d_in, const int* in_sizes, int n_in,
                              void* d_out, int out_size) {
    // inputs: 0=t(1), 1=state(2*NX*NY), 2=x(NX), 3=y(NY), 4=mu(1)
    const float* x_g   = (const float*)d_in[2];
    const float* y_g   = (const float*)d_in[3];
    const float* state = (const float*)d_in[1];
    const float* mu    = (const float*)d_in[4];
    float* out = (float*)d_out;

    dim3 blk(32, 4);                          // 128 threads
    dim3 grd((NY / 4) / 32, NX / (4 * ROWS)); // (32, 64)
    rhs_kernel<<<grd, blk>>>(state, x_g, y_g, mu, out);
}

// round 10
// speedup vs baseline: 1.3700x; 1.3700x over previous
#include <cuda_runtime.h>
#include <cuda_bf16.h>

#define NX 2048
#define NY 4096
#define ROWS 8
#define FULLMASK 0xffffffffu

// Build c1/c2 from ha, hb, inv = 1/(ha*hb*(ha+hb)).
// kind: 0 = left one-sided, 1 = centered, 2 = right one-sided
__device__ __forceinline__ void coeffs_from_inv(float ha, float hb, float inv, int kind,
                                                float c1[3], float c2[3]) {
    float sab = ha + hb;
    float i_a  = hb  * inv;
    float i_ab = sab * inv;
    float i_b  = ha  * inv;
    c2[0] = 2.0f * i_a;
    c2[1] = -2.0f * i_ab;
    c2[2] = 2.0f * i_b;
    if (kind == 0) {
        c1[0] = -(2.0f * ha + hb) * i_a;
        c1[1] = sab * i_ab;
        c1[2] = -ha * i_b;
    } else if (kind == 2) {
        c1[0] = hb * i_a;
        c1[1] = -sab * i_ab;
        c1[2] = (ha + 2.0f * hb) * i_b;
    } else {
        c1[0] = -hb * i_a;
        c1[1] = (hb - ha) * i_ab;
        c1[2] = ha * i_b;
    }
}

// Each thread: 4 consecutive j (float4) x 8 i rows, rolling 4-row window.
// mu is pre-folded into all second-derivative coefficients.
__global__ __launch_bounds__(128, 5) void rhs_kernel(const float* __restrict__ state,
                                                     const float* __restrict__ xg,
                                                     const float* __restrict__ yg,
                                                     const float* __restrict__ mu_p,
                                                     float* __restrict__ out) {
    const int lane = threadIdx.x;                       // 0..31
    const int jg = blockIdx.x * 32 + lane;
    const int j0 = jg * 4;
    const int it = blockIdx.y * blockDim.y + threadIdx.y;
    const int i0 = it * ROWS;

    const float* __restrict__ u = state;
    const float* __restrict__ v = state + NX * NY;

    const bool eL = (j0 == 0);
    const bool eR = (j0 == NY - 4);
    const bool firstB = (i0 == 0);
    const bool lastB  = (i0 == NX - ROWS);
    const float mu = mu_p[0];

    // ---- rolling window prologue: rows clamp(i0-1), i0, i0+1, i0+2 ----
    int rA = max(i0 - 1, 0);
    float4 Au = *(const float4*)(u + rA * NY + j0);
    float4 Av = *(const float4*)(v + rA * NY + j0);
    float4 Bu = *(const float4*)(u + i0 * NY + j0);
    float4 Bv = *(const float4*)(v + i0 * NY + j0);
    float4 Cu = *(const float4*)(u + (i0 + 1) * NY + j0);
    float4 Cv = *(const float4*)(v + (i0 + 1) * NY + j0);
    float4 Du = *(const float4*)(u + (i0 + 2) * NY + j0);
    float4 Dv = *(const float4*)(v + (i0 + 2) * NY + j0);

    // ---- y coefficients (pair-batched: 2 RCPs); mu folded into C2Y ----
    float C1Y0[4], C1Y1[4], C1Y2[4], C2Y0[4], C2Y1[4], C2Y2[4];
    {
        float ys[6];
#pragma unroll
        for (int t = 0; t < 6; t++)
            ys[t] = yg[min(max(j0 - 1 + t, 0), NY - 1)];
        float HA[4], HB[4], T[4];
        int KND[4];
#pragma unroll
        for (int l = 0; l < 4; l++) {
            float g0 = ys[l], g1 = ys[l + 1], g2 = ys[l + 2];
            int kind = 1;
            if (l == 0 && eL) { g0 = ys[1]; g1 = ys[2]; g2 = ys[3]; kind = 0; }
            if (l == 3 && eR) { g0 = ys[2]; g1 = ys[3]; g2 = ys[4]; kind = 2; }
            HA[l] = g1 - g0;
            HB[l] = g2 - g1;
            T[l] = HA[l] * HB[l] * (HA[l] + HB[l]);
            KND[l] = kind;
        }
        float ip01 = 1.0f / (T[0] * T[1]);
        float ip23 = 1.0f / (T[2] * T[3]);
        float INV[4] = {ip01 * T[1], ip01 * T[0], ip23 * T[3], ip23 * T[2]};
#pragma unroll
        for (int l = 0; l < 4; l++) {
            float c1[3], c2[3];
            coeffs_from_inv(HA[l], HB[l], INV[l], KND[l], c1, c2);
            C1Y0[l] = c1[0]; C1Y1[l] = c1[1]; C1Y2[l] = c1[2];
            C2Y0[l] = mu * c2[0]; C2Y1[l] = mu * c2[1]; C2Y2[l] = mu * c2[2];
        }
    }

    // ---- x coefficients: each lane computes ONE row's set (row = lane&7), 1 RCP ----
    float cx1p[3], cx2p[3];
    {
        int ii = i0 + (lane & 7);
        int s = min(max(ii - 1, 0), NX - 3);
        int kind = (ii == 0) ? 0 : ((ii == NX - 1) ? 2 : 1);
        float g0 = xg[s], g1 = xg[s + 1], g2 = xg[s + 2];
        float ha = g1 - g0, hb = g2 - g1;
        float inv = 1.0f / (ha * hb * (ha + hb));
        coeffs_from_inv(ha, hb, inv, kind, cx1p, cx2p);
        cx2p[0] *= mu; cx2p[1] *= mu; cx2p[2] *= mu;
    }

    // j-dependent boundary predicates (loop-invariant over rows)
    bool zj[4], zlast[4];
#pragma unroll
    for (int l = 0; l < 4; l++) {
        zj[l]    = (j0 + l == 0);
        zlast[l] = (j0 + l == NY - 1);
    }

    int off = i0 * NY + j0;

#pragma unroll
    for (int m = 0; m < ROWS; m++) {
        const int i = i0 + m;

        // x coefficients for this row: broadcast within 8-lane groups
        const float cx10 = __shfl_sync(FULLMASK, cx1p[0], m, 8);
        const float cx11 = __shfl_sync(FULLMASK, cx1p[1], m, 8);
        const float cx12 = __shfl_sync(FULLMASK, cx1p[2], m, 8);
        const float cx20 = __shfl_sync(FULLMASK, cx2p[0], m, 8);
        const float cx21 = __shfl_sync(FULLMASK, cx2p[1], m, 8);
        const float cx22 = __shfl_sync(FULLMASK, cx2p[2], m, 8);

        // select x-stencil data rows (window: A=i-1, B=i, C=i+1, D=i+2)
        float4 u0 = Au, u1 = Bu, u2 = Cu;
        float4 v0 = Av, v1 = Bv, v2 = Cv;
        if (m == 0 && firstB) {            // i==0: data rows 0,1,2
            u0 = Bu; u1 = Cu; u2 = Du;
            v0 = Bv; v1 = Cv; v2 = Dv;
        }
        if (m == ROWS - 1 && lastB) {      // i==NX-1: data rows NX-3,NX-2,NX-1
            float4 zu = *(const float4*)(u + (NX - 3) * NY + j0);
            float4 zv = *(const float4*)(v + (NX - 3) * NY + j0);
            u0 = zu; u1 = Au; u2 = Bu;
            v0 = zv; v1 = Av; v2 = Bv;
        }

        // center row (global i) is always B
        const float4 uc = Bu;
        const float4 vc = Bv;

        // y-neighbors via warp shuffle, patched at warp edges
        float uLm = __shfl_up_sync(FULLMASK, uc.w, 1);
        float vLm = __shfl_up_sync(FULLMASK, vc.w, 1);
        float uRm = __shfl_down_sync(FULLMASK, uc.x, 1);
        float vRm = __shfl_down_sync(FULLMASK, vc.x, 1);
        if (lane == 0 && j0 > 0) {
            uLm = u[off - 1];
            vLm = v[off - 1];
        }
        if (lane == 31 && j0 + 4 < NY) {
            uRm = u[off + 4];
            vRm = v[off + 4];
        }

        const float u_vals[6] = {uLm, uc.x, uc.y, uc.z, uc.w, uRm};
        const float v_vals[6] = {vLm, vc.x, vc.y, vc.z, vc.w, vRm};
        const float AX0[4] = {u0.x, u0.y, u0.z, u0.w};
        const float AX1[4] = {u1.x, u1.y, u1.z, u1.w};
        const float AX2[4] = {u2.x, u2.y, u2.z, u2.w};
        const float BX0[4] = {v0.x, v0.y, v0.z, v0.w};
        const float BX1[4] = {v1.x, v1.y, v1.z, v1.w};
        const float BX2[4] = {v2.x, v2.y, v2.z, v2.w};

        float du[4], dv[4];
#pragma unroll
        for (int l = 0; l < 4; l++) {
            float f0 = u_vals[l], f1 = u_vals[l + 1], f2 = u_vals[l + 2];
            float g0 = v_vals[l], g1 = v_vals[l + 1], g2 = v_vals[l + 2];
            if (eL && l == 0) {         // one-sided at j=0: data points 0,1,2
                f0 = u_vals[1]; f1 = u_vals[2]; f2 = u_vals[3];
                g0 = v_vals[1]; g1 = v_vals[2]; g2 = v_vals[3];
            }
            if (eR && l == 3) {         // one-sided at j=NY-1: data NY-3..NY-1
                f0 = u_vals[2]; f1 = u_vals[3]; f2 = u_vals[4];
                g0 = v_vals[2]; g1 = v_vals[3]; g2 = v_vals[4];
            }

            float d1yu = C1Y0[l] * f0 + C1Y1[l] * f1 + C1Y2[l] * f2;
            float d2yu = C2Y0[l] * f0 + C2Y1[l] * f1 + C2Y2[l] * f2;   // mu-scaled
            float d1yv = C1Y0[l] * g0 + C1Y1[l] * g1 + C1Y2[l] * g2;
            float d2yv = C2Y0[l] * g0 + C2Y1[l] * g1 + C2Y2[l] * g2;   // mu-scaled

            float d1xu = cx10 * AX0[l] + cx11 * AX1[l] + cx12 * AX2[l];
            float d2xu = cx20 * AX0[l] + cx21 * AX1[l] + cx22 * AX2[l]; // mu-scaled
            float d1xv = cx10 * BX0[l] + cx11 * BX1[l] + cx12 * BX2[l];
            float d2xv = cx20 * BX0[l] + cx21 * BX1[l] + cx22 * BX2[l]; // mu-scaled

            float ucen = u_vals[l + 1];
            float vcen = v_vals[l + 1];

            du[l] = (d2yu + d2xu) - ucen * d1xu - vcen * d1yu + 0.01f;
            dv[l] = (d2yv + d2xv) - ucen * d1xv - vcen * d1yv;

            bool zi = (m == 0) && firstB;            // i == 0
            if (zj[l] || zi) { du[l] = 0.0f; dv[l] = 0.0f; }
            if (zlast[l]) du[l] = 0.0f;
        }

        *(float4*)(out + off) = make_float4(du[0], du[1], du[2], du[3]);
        *(float4*)(out + NX * NY + off) = make_float4(dv[0], dv[1], dv[2], dv[3]);

        // shift window and prefetch next row (D becomes row i+3 of new window)
        if (m < ROWS - 1) {
            Au = Bu; Bu = Cu; Cu = Du;
            Av = Bv; Bv = Cv; Cv = Dv;
            int r = min(i + 3, NX - 1);
            Du = *(const float4*)(u + r * NY + j0);
            Dv = *(const float4*)(v + r * NY + j0);
            off += NY;
        }
    }
}

extern "C" void kernel_launch(void* const* d_in, const int* in_sizes, int n_in,
                              void* d_out, int out_size) {
    // inputs: 0=t(1), 1=state(2*NX*NY), 2=x(NX), 3=y(NY), 4=mu(1)
    const float* x_g   = (const float*)d_in[2];
    const float* y_g   = (const float*)d_in[3];
    const float* state = (const float*)d_in[1];
    const float* mu    = (const float*)d_in[4];
    float* out = (float*)d_out;

    dim3 blk(32, 4);                          // 128 threads
    dim3 grd((NY / 4) / 32, NX / (4 * ROWS)); // (32, 64)
    rhs_kernel<<<grd, blk>>>(state, x_g, y_g, mu, out);
}